// round 5
// baseline (speedup 1.0000x reference)
#include <cuda_runtime.h>

#define BLK  64      // 2 warps/CTA; each thread owns a PAIR of batch elements
#define ROWW 146     // floats per pair-row; 146 ≡ 18 (mod 32) -> LDS.64 conflict-free

typedef unsigned long long ull;

// ---- packed fp32x2 primitives (sm_103a) -----------------------------------
__device__ __forceinline__ ull pk2(float lo, float hi) {
    ull r; asm("mov.b64 %0, {%1,%2};" : "=l"(r) : "f"(lo), "f"(hi)); return r;
}
__device__ __forceinline__ void upk2(ull v, float& lo, float& hi) {
    asm("mov.b64 {%0,%1}, %2;" : "=f"(lo), "=f"(hi) : "l"(v));
}
__device__ __forceinline__ ull f2fma(ull a, ull b, ull c) {
    ull d; asm("fma.rn.f32x2 %0, %1, %2, %3;" : "=l"(d) : "l"(a), "l"(b), "l"(c)); return d;
}
__device__ __forceinline__ ull f2mul(ull a, ull b) {
    ull d; asm("mul.rn.f32x2 %0, %1, %2;" : "=l"(d) : "l"(a), "l"(b)); return d;
}
__device__ __forceinline__ ull f2add(ull a, ull b) {
    ull d; asm("add.rn.f32x2 %0, %1, %2;" : "=l"(d) : "l"(a), "l"(b)); return d;
}

// Broadcast-packed polynomial constants (built once per thread, kept in regs).
struct C2 {
    ull one, neg1, half;
    ull a3, a2, a1, a0;     // sin(sqrt u)/sqrt u coeffs (degree-4 in u)
    ull b3, b2, b1, b0;     // (1-cos(sqrt u))/u coeffs (degree-4 in u)
};

// In-row word index for logical float w (= 3*joint + comp), half h:
//   word = 36*(w&3) + 2*(w>>2) + h   -> ull index = 18*(w&3) + (w>>2)
// i-major interleave keeps stage/drain smem ops nearly conflict-free while
// compute offsets fold to compile-time constants.
__device__ __forceinline__ ull ldw(const float* row, int w) {
    return *reinterpret_cast<const ull*>(row + 36 * (w & 3) + 2 * (w >> 2));
}
__device__ __forceinline__ void stw(float* row, int w, ull v) {
    *reinterpret_cast<ull*>(row + 36 * (w & 3) + 2 * (w >> 2)) = v;
}

// ---- packed Rodrigues (no sqrt/sin/cos; degree-4 Taylor in u = |r|^2) -----
__device__ __forceinline__ void rodr2(ull x, ull y, ull z, ull R[9], const C2& K) {
    const ull u = f2fma(x, x, f2fma(y, y, f2mul(z, z)));

    ull A = f2fma(u, K.a3, K.a2);
    A = f2fma(A, u, K.a1);
    A = f2fma(A, u, K.a0);
    A = f2fma(A, u, K.one);

    ull Bv = f2fma(u, K.b3, K.b2);
    Bv = f2fma(Bv, u, K.b1);
    Bv = f2fma(Bv, u, K.b0);
    Bv = f2fma(Bv, u, K.half);

    const ull uB = f2mul(u, Bv);
    const ull c  = f2fma(uB, K.neg1, K.one);          // 1 - u*B
    const ull Bx = f2mul(Bv, x), By = f2mul(Bv, y), Bz = f2mul(Bv, z);
    const ull Ax = f2mul(A, x),  Ay = f2mul(A, y),  Az = f2mul(A, z);
    const ull Bxy = f2mul(Bx, y), Bxz = f2mul(Bx, z), Byz = f2mul(By, z);

    R[0] = f2fma(Bx, x, c);
    R[4] = f2fma(By, y, c);
    R[8] = f2fma(Bz, z, c);
    R[1] = f2fma(Az, K.neg1, Bxy);  R[3] = f2add(Bxy, Az);
    R[2] = f2add(Bxz, Ay);          R[6] = f2fma(Ay, K.neg1, Bxz);
    R[5] = f2fma(Ax, K.neg1, Byz);  R[7] = f2add(Byz, Ax);
}

// Non-leaf joint J: t' = G*off + t (emit); G' = G * R(pose_J).
template <int J>
__device__ __forceinline__ void stepNL2(ull G[9], ull t[3], float* __restrict__ row,
                                        const ull (*__restrict__ off)[3], const C2& K) {
    const ull ox = off[J][0], oy = off[J][1], oz = off[J][2];
    const ull n0 = f2fma(G[0], ox, f2fma(G[1], oy, f2fma(G[2], oz, t[0])));
    const ull n1 = f2fma(G[3], ox, f2fma(G[4], oy, f2fma(G[5], oz, t[1])));
    const ull n2 = f2fma(G[6], ox, f2fma(G[7], oy, f2fma(G[8], oz, t[2])));

    ull R[9];
    rodr2(ldw(row, 3*J+0), ldw(row, 3*J+1), ldw(row, 3*J+2), R, K);

#pragma unroll
    for (int r = 0; r < 3; r++) {
        const ull g0 = G[3*r], g1 = G[3*r+1], g2 = G[3*r+2];
        G[3*r+0] = f2fma(g0, R[0], f2fma(g1, R[3], f2mul(g2, R[6])));
        G[3*r+1] = f2fma(g0, R[1], f2fma(g1, R[4], f2mul(g2, R[7])));
        G[3*r+2] = f2fma(g0, R[2], f2fma(g1, R[5], f2mul(g2, R[8])));
    }

    t[0] = n0; t[1] = n1; t[2] = n2;
    stw(row, 3*J+0, n0); stw(row, 3*J+1, n1); stw(row, 3*J+2, n2);
}

// Leaf joint J: position only.
template <int J>
__device__ __forceinline__ void stepLeaf2(const ull G[9], const ull t[3],
                                          float* __restrict__ row,
                                          const ull (*__restrict__ off)[3]) {
    const ull ox = off[J][0], oy = off[J][1], oz = off[J][2];
    stw(row, 3*J+0, f2fma(G[0], ox, f2fma(G[1], oy, f2fma(G[2], oz, t[0]))));
    stw(row, 3*J+1, f2fma(G[3], ox, f2fma(G[4], oy, f2fma(G[5], oz, t[1]))));
    stw(row, 3*J+2, f2fma(G[6], ox, f2fma(G[7], oy, f2fma(G[8], oz, t[2]))));
}

__global__ void __launch_bounds__(BLK)
skel_kernel(const float* __restrict__ pose,
            const float* __restrict__ trans,
            const float* __restrict__ Jm,
            float* __restrict__ out, int B) {
    __shared__ __align__(16) float s[2 * 32 * ROWW];   // 2 warps x 32 pair-rows
    __shared__ ull off2[24][3];

    const int tid  = threadIdx.x;
    const int lane = tid & 31;
    const int wrp  = tid >> 5;
    const int wE   = blockIdx.x * (BLK * 2) + wrp * 64;   // warp's 64 elements
    const int e0   = wE + 2 * lane;                       // this thread's pair

    if (tid < 24) {
        const float ox = Jm[tid*16 + 3], oy = Jm[tid*16 + 7], oz = Jm[tid*16 + 11];
        off2[tid][0] = pk2(ox, ox);
        off2[tid][1] = pk2(oy, oy);
        off2[tid][2] = pk2(oz, oz);
    }

    // Hoisted trans loads for this thread's two elements.
    float ta0 = 0.f, ta1 = 0.f, ta2 = 0.f, tb0 = 0.f, tb1 = 0.f, tb2 = 0.f;
    if (e0 < B)     { ta0 = trans[e0*3+0]; ta1 = trans[e0*3+1]; ta2 = trans[e0*3+2]; }
    if (e0 + 1 < B) { tb0 = trans[e0*3+3]; tb1 = trans[e0*3+4]; tb2 = trans[e0*3+5]; }

    // --- Stage: coalesced float4 loads, pack element pairs into smem rows --
    const float4* gp = reinterpret_cast<const float4*>(pose);
    float* sw = &s[wrp * 32 * ROWW];
#pragma unroll
    for (int k = 0; k < 18; k++) {
        const int v = lane + 32 * k;     // (pair r, float4 c4): 32*18 = 576 combos
        const int r = v / 18, c4 = v % 18;
        const int ea = wE + 2 * r;
        float4 qa = make_float4(0.f, 0.f, 0.f, 0.f), qb = qa;
        if (ea < B)     qa = gp[ea * 18 + c4];
        if (ea + 1 < B) qb = gp[ea * 18 + 18 + c4];
        ull* d = reinterpret_cast<ull*>(sw + r * ROWW);
        d[      c4] = pk2(qa.x, qb.x);   // word 4c4+0 -> i-major slot 18*0+c4
        d[18 +  c4] = pk2(qa.y, qb.y);
        d[36 +  c4] = pk2(qa.z, qb.z);
        d[54 +  c4] = pk2(qa.w, qb.w);
    }
    __syncthreads();   // publish off2 + staged pose

    // --- Packed tree walk: 18 composes + 6 leaf mat-vecs, 2 elements/thread -
    {
        C2 K;
        K.one  = pk2( 1.0f, 1.0f);
        K.neg1 = pk2(-1.0f, -1.0f);
        K.half = pk2( 0.5f, 0.5f);
        K.a3 = pk2( 2.75573192e-6f,  2.75573192e-6f);
        K.a2 = pk2(-1.98412698e-4f, -1.98412698e-4f);
        K.a1 = pk2( 8.33333333e-3f,  8.33333333e-3f);
        K.a0 = pk2(-1.66666667e-1f, -1.66666667e-1f);
        K.b3 = pk2( 2.75573192e-7f,  2.75573192e-7f);
        K.b2 = pk2(-2.48015873e-5f, -2.48015873e-5f);
        K.b1 = pk2( 1.38888889e-3f,  1.38888889e-3f);
        K.b0 = pk2(-4.16666667e-2f, -4.16666667e-2f);

        float* row = sw + lane * ROWW;
        ull G[9], t[3], S[9], st[3];

        // Root: G = R(pose_0); t = off_0 + trans (trans folds into root).
        rodr2(ldw(row, 0), ldw(row, 1), ldw(row, 2), G, K);
        t[0] = f2add(off2[0][0], pk2(ta0, tb0));
        t[1] = f2add(off2[0][1], pk2(ta1, tb1));
        t[2] = f2add(off2[0][2], pk2(ta2, tb2));
        stw(row, 0, t[0]); stw(row, 1, t[1]); stw(row, 2, t[2]);

#pragma unroll
        for (int i = 0; i < 9; i++) S[i] = G[i];
        st[0] = t[0]; st[1] = t[1]; st[2] = t[2];

        // Left leg: 1 -> 4 -> 7 -> 10(leaf)
        stepNL2<1>(G, t, row, off2, K);
        stepNL2<4>(G, t, row, off2, K);
        stepNL2<7>(G, t, row, off2, K);
        stepLeaf2<10>(G, t, row, off2);

        // Right leg: 2 -> 5 -> 8 -> 11(leaf)
#pragma unroll
        for (int i = 0; i < 9; i++) G[i] = S[i];
        t[0] = st[0]; t[1] = st[1]; t[2] = st[2];
        stepNL2<2>(G, t, row, off2, K);
        stepNL2<5>(G, t, row, off2, K);
        stepNL2<8>(G, t, row, off2, K);
        stepLeaf2<11>(G, t, row, off2);

        // Spine: 3 -> 6 -> 9 (branch point)
#pragma unroll
        for (int i = 0; i < 9; i++) G[i] = S[i];
        t[0] = st[0]; t[1] = st[1]; t[2] = st[2];
        stepNL2<3>(G, t, row, off2, K);
        stepNL2<6>(G, t, row, off2, K);
        stepNL2<9>(G, t, row, off2, K);
#pragma unroll
        for (int i = 0; i < 9; i++) S[i] = G[i];
        st[0] = t[0]; st[1] = t[1]; st[2] = t[2];

        // Head: 12 -> 15(leaf)
        stepNL2<12>(G, t, row, off2, K);
        stepLeaf2<15>(G, t, row, off2);

        // Left arm: 13 -> 16 -> 18 -> 20 -> 22(leaf)
#pragma unroll
        for (int i = 0; i < 9; i++) G[i] = S[i];
        t[0] = st[0]; t[1] = st[1]; t[2] = st[2];
        stepNL2<13>(G, t, row, off2, K);
        stepNL2<16>(G, t, row, off2, K);
        stepNL2<18>(G, t, row, off2, K);
        stepNL2<20>(G, t, row, off2, K);
        stepLeaf2<22>(G, t, row, off2);

        // Right arm: 14 -> 17 -> 19 -> 21 -> 23(leaf) — consumes S in place.
        stepNL2<14>(S, st, row, off2, K);
        stepNL2<17>(S, st, row, off2, K);
        stepNL2<19>(S, st, row, off2, K);
        stepNL2<21>(S, st, row, off2, K);
        stepLeaf2<23>(S, st, row, off2);
    }
    __syncwarp();   // drain reads only this warp's rows

    // --- Drain: unpack pair rows -> coalesced float4 stores ----------------
    float4* go = reinterpret_cast<float4*>(out);
#pragma unroll
    for (int k = 0; k < 18; k++) {
        const int v = lane + 32 * k;
        const int r = v / 18, c4 = v % 18;
        const ull* dr = reinterpret_cast<const ull*>(sw + r * ROWW);
        const ull wx = dr[c4], wy = dr[18 + c4], wz = dr[36 + c4], ww = dr[54 + c4];
        float ax, bx, ay, by, az, bz, aw, bw;
        upk2(wx, ax, bx); upk2(wy, ay, by); upk2(wz, az, bz); upk2(ww, aw, bw);
        const int ea = wE + 2 * r;
        if (ea < B)     go[ea * 18 + c4]      = make_float4(ax, ay, az, aw);
        if (ea + 1 < B) go[ea * 18 + 18 + c4] = make_float4(bx, by, bz, bw);
    }
}

extern "C" void kernel_launch(void* const* d_in, const int* in_sizes, int n_in,
                              void* d_out, int out_size) {
    // Identify inputs by element count (expected order: pose, trans, J, parents)
    int ip = 0;
    long long mx = -1;
    for (int i = 0; i < n_in; i++)
        if ((long long)in_sizes[i] > mx) { mx = in_sizes[i]; ip = i; }
    const int B = in_sizes[ip] / 72;            // pose: [B,24,3]

    int it = -1, ij = -1;
    for (int i = 0; i < n_in; i++) {
        if (i == ip) continue;
        if (in_sizes[i] == B * 3) it = i;        // trans: [B,3]
        else if (in_sizes[i] == 24 * 16) ij = i; // J: [24,4,4]
    }
    if (it < 0) it = 1;
    if (ij < 0) ij = 2;

    cudaFuncSetAttribute(skel_kernel,
                         cudaFuncAttributePreferredSharedMemoryCarveout, 100);

    const int grid = (B + BLK * 2 - 1) / (BLK * 2);   // 128 elements per CTA
    skel_kernel<<<grid, BLK>>>((const float*)d_in[ip],
                               (const float*)d_in[it],
                               (const float*)d_in[ij],
                               (float*)d_out, B);
}

// round 6
// speedup vs baseline: 1.0017x; 1.0017x over previous
#include <cuda_runtime.h>

#define BLK 128
#define ROW 73   // padded smem row stride; tid*73 mod 32 ≡ tid*9, gcd(9,32)=1 -> conflict-free

typedef unsigned long long ull;

// ---- packed fp32x2 primitives (sm_103a) -----------------------------------
__device__ __forceinline__ ull pk2(float lo, float hi) {
    ull r; asm("mov.b64 %0, {%1,%2};" : "=l"(r) : "f"(lo), "f"(hi)); return r;
}
__device__ __forceinline__ void upk2(ull v, float& lo, float& hi) {
    asm("mov.b64 {%0,%1}, %2;" : "=f"(lo), "=f"(hi) : "l"(v));
}
__device__ __forceinline__ ull f2fma(ull a, ull b, ull c) {
    ull d; asm("fma.rn.f32x2 %0, %1, %2, %3;" : "=l"(d) : "l"(a), "l"(b), "l"(c)); return d;
}
__device__ __forceinline__ ull f2mul(ull a, ull b) {
    ull d; asm("mul.rn.f32x2 %0, %1, %2;" : "=l"(d) : "l"(a), "l"(b)); return d;
}
__device__ __forceinline__ ull f2add(ull a, ull b) {
    ull d; asm("add.rn.f32x2 %0, %1, %2;" : "=l"(d) : "l"(a), "l"(b)); return d;
}

// ---- scalar Taylor polys (immediate constants -> zero constant registers) -
// A = sin(sqrt u)/sqrt u, B = (1-cos(sqrt u))/u, degree-4 in u = |r|^2.
__device__ __forceinline__ float polyA(float u) {
    float A = fmaf(u,  2.75573192e-6f, -1.98412698e-4f);
    A = fmaf(A, u,  8.33333333e-3f);
    A = fmaf(A, u, -1.66666667e-1f);
    return fmaf(A, u, 1.0f);
}
__device__ __forceinline__ float polyB(float u) {
    float Bv = fmaf(u,  2.75573192e-7f, -2.48015873e-5f);
    Bv = fmaf(Bv, u,  1.38888889e-3f);
    Bv = fmaf(Bv, u, -4.16666667e-2f);
    return fmaf(Bv, u, 0.5f);
}

// ---- scalar Rodrigues ------------------------------------------------------
__device__ __forceinline__ void rodr3(float x, float y, float z, float R[9]) {
    const float u = fmaf(x, x, fmaf(y, y, z * z));
    const float A = polyA(u), Bv = polyB(u);
    const float c = fmaf(-Bv, u, 1.0f);
    const float Bx = Bv * x, By = Bv * y, Bz = Bv * z;
    const float Ax = A * x,  Ay = A * y,  Az = A * z;
    const float Bxy = Bx * y, Bxz = Bx * z, Byz = By * z;
    R[0] = fmaf(Bx, x, c);  R[4] = fmaf(By, y, c);  R[8] = fmaf(Bz, z, c);
    R[1] = Bxy - Az;  R[3] = Bxy + Az;
    R[2] = Bxz + Ay;  R[6] = Bxz - Ay;
    R[5] = Byz - Ax;  R[7] = Byz + Ax;
}

// ---- packed Rodrigues: poly scalar per half, matrix build packed ----------
__device__ __forceinline__ void rodr2(ull x, ull y, ull z, ull R[9], ull neg1) {
    const ull u = f2fma(x, x, f2fma(y, y, f2mul(z, z)));
    float ul, uh; upk2(u, ul, uh);
    const float Al = polyA(ul), Ah = polyA(uh);
    const float Bl = polyB(ul), Bh = polyB(uh);
    const ull A  = pk2(Al, Ah);
    const ull Bv = pk2(Bl, Bh);
    const ull c  = pk2(fmaf(-Bl, ul, 1.0f), fmaf(-Bh, uh, 1.0f));

    const ull Bx = f2mul(Bv, x), By = f2mul(Bv, y), Bz = f2mul(Bv, z);
    const ull Ax = f2mul(A, x),  Ay = f2mul(A, y),  Az = f2mul(A, z);
    const ull Bxy = f2mul(Bx, y), Bxz = f2mul(Bx, z), Byz = f2mul(By, z);

    R[0] = f2fma(Bx, x, c);  R[4] = f2fma(By, y, c);  R[8] = f2fma(Bz, z, c);
    R[1] = f2fma(Az, neg1, Bxy);  R[3] = f2add(Bxy, Az);
    R[2] = f2add(Bxz, Ay);        R[6] = f2fma(Ay, neg1, Bxz);
    R[5] = f2fma(Ax, neg1, Byz);  R[7] = f2add(Byz, Ax);
}

// ---- scalar non-leaf / leaf steps (R1-proven form) -------------------------
template <int J>
__device__ __forceinline__ void stepNL(float G[9], float t[3],
                                       float* __restrict__ mp,
                                       const float4* __restrict__ off4) {
    const float4 o = off4[J];
    const float n0 = fmaf(G[0], o.x, fmaf(G[1], o.y, fmaf(G[2], o.z, t[0])));
    const float n1 = fmaf(G[3], o.x, fmaf(G[4], o.y, fmaf(G[5], o.z, t[1])));
    const float n2 = fmaf(G[6], o.x, fmaf(G[7], o.y, fmaf(G[8], o.z, t[2])));
    float R[9];
    rodr3(mp[J*3+0], mp[J*3+1], mp[J*3+2], R);
#pragma unroll
    for (int r = 0; r < 3; r++) {
        const float g0 = G[r*3+0], g1 = G[r*3+1], g2 = G[r*3+2];
        G[r*3+0] = fmaf(g0, R[0], fmaf(g1, R[3], g2 * R[6]));
        G[r*3+1] = fmaf(g0, R[1], fmaf(g1, R[4], g2 * R[7]));
        G[r*3+2] = fmaf(g0, R[2], fmaf(g1, R[5], g2 * R[8]));
    }
    t[0] = n0; t[1] = n1; t[2] = n2;
    mp[J*3+0] = n0; mp[J*3+1] = n1; mp[J*3+2] = n2;
}
template <int J>
__device__ __forceinline__ void stepLeaf(const float G[9], const float t[3],
                                         float* __restrict__ mp,
                                         const float4* __restrict__ off4) {
    const float4 o = off4[J];
    mp[J*3+0] = fmaf(G[0], o.x, fmaf(G[1], o.y, fmaf(G[2], o.z, t[0])));
    mp[J*3+1] = fmaf(G[3], o.x, fmaf(G[4], o.y, fmaf(G[5], o.z, t[1])));
    mp[J*3+2] = fmaf(G[6], o.x, fmaf(G[7], o.y, fmaf(G[8], o.z, t[2])));
}

// ---- packed pair steps: joints (J, J+1), pair index P ----------------------
template <int J, int P>
__device__ __forceinline__ void stepPair(ull G[9], ull t[3],
                                         float* __restrict__ mp,
                                         const ull (*__restrict__ offp)[3],
                                         ull neg1) {
    const ull ox = offp[P][0], oy = offp[P][1], oz = offp[P][2];
    const ull n0 = f2fma(G[0], ox, f2fma(G[1], oy, f2fma(G[2], oz, t[0])));
    const ull n1 = f2fma(G[3], ox, f2fma(G[4], oy, f2fma(G[5], oz, t[1])));
    const ull n2 = f2fma(G[6], ox, f2fma(G[7], oy, f2fma(G[8], oz, t[2])));

    // packed pose: lo half = joint J, hi half = joint J+1
    const ull px = pk2(mp[3*J+0], mp[3*J+3]);
    const ull py = pk2(mp[3*J+1], mp[3*J+4]);
    const ull pz = pk2(mp[3*J+2], mp[3*J+5]);
    ull R[9];
    rodr2(px, py, pz, R, neg1);

#pragma unroll
    for (int r = 0; r < 3; r++) {
        const ull g0 = G[r*3+0], g1 = G[r*3+1], g2 = G[r*3+2];
        G[r*3+0] = f2fma(g0, R[0], f2fma(g1, R[3], f2mul(g2, R[6])));
        G[r*3+1] = f2fma(g0, R[1], f2fma(g1, R[4], f2mul(g2, R[7])));
        G[r*3+2] = f2fma(g0, R[2], f2fma(g1, R[5], f2mul(g2, R[8])));
    }
    t[0] = n0; t[1] = n1; t[2] = n2;
    float a, b;
    upk2(n0, a, b); mp[3*J+0] = a; mp[3*J+3] = b;
    upk2(n1, a, b); mp[3*J+1] = a; mp[3*J+4] = b;
    upk2(n2, a, b); mp[3*J+2] = a; mp[3*J+5] = b;
}
template <int J, int P>
__device__ __forceinline__ void leafPair(const ull G[9], const ull t[3],
                                         float* __restrict__ mp,
                                         const ull (*__restrict__ offp)[3]) {
    const ull ox = offp[P][0], oy = offp[P][1], oz = offp[P][2];
    const ull n0 = f2fma(G[0], ox, f2fma(G[1], oy, f2fma(G[2], oz, t[0])));
    const ull n1 = f2fma(G[3], ox, f2fma(G[4], oy, f2fma(G[5], oz, t[1])));
    const ull n2 = f2fma(G[6], ox, f2fma(G[7], oy, f2fma(G[8], oz, t[2])));
    float a, b;
    upk2(n0, a, b); mp[3*J+0] = a; mp[3*J+3] = b;
    upk2(n1, a, b); mp[3*J+1] = a; mp[3*J+4] = b;
    upk2(n2, a, b); mp[3*J+2] = a; mp[3*J+5] = b;
}

// First joints of the 9 symmetric pairs (second is +1).
__device__ __constant__ int PAIRJ[9] = {1, 4, 7, 10, 13, 16, 18, 20, 22};

__global__ void __launch_bounds__(BLK, 4)
skel_kernel(const float* __restrict__ pose,
            const float* __restrict__ trans,
            const float* __restrict__ Jm,
            float* __restrict__ out, int B) {
    __shared__ float  s[BLK * ROW];
    __shared__ float4 off4[24];
    __shared__ ull    offp[9][3];

    const int tid  = threadIdx.x;
    const int lane = tid & 31;
    const int wrp  = tid >> 5;
    const int b0   = blockIdx.x * BLK;
    const int wb0  = b0 + wrp * 32;
    const int myb  = b0 + tid;
    const bool inb = (myb < B);

    // Hoisted DRAM loads.
    float tr0 = 0.f, tr1 = 0.f, tr2 = 0.f;
    if (inb) { tr0 = trans[myb*3+0]; tr1 = trans[myb*3+1]; tr2 = trans[myb*3+2]; }
    if (tid < 24)
        off4[tid] = make_float4(Jm[tid*16+3], Jm[tid*16+7], Jm[tid*16+11], 0.f);
    if (tid >= 32 && tid < 41) {          // build packed pair offsets (warp 1)
        const int p  = tid - 32;
        const int j1 = PAIRJ[p];
        offp[p][0] = pk2(Jm[j1*16+3],  Jm[(j1+1)*16+3]);
        offp[p][1] = pk2(Jm[j1*16+7],  Jm[(j1+1)*16+7]);
        offp[p][2] = pk2(Jm[j1*16+11], Jm[(j1+1)*16+11]);
    }

    // --- Stage pose: coalesced float4 loads -> padded smem rows (R1 form) --
    const float4* gp = reinterpret_cast<const float4*>(pose) + (long long)wb0 * 18;
    float* sw = &s[wrp * 32 * ROW];
#pragma unroll
    for (int k = 0; k < 18; k++) {
        const int v = lane + k * 32;
        const int b = v / 18, c = v % 18;
        if (wb0 + b < B) {
            const float4 q = gp[v];
            float* d = &sw[b * ROW + c * 4];
            d[0] = q.x; d[1] = q.y; d[2] = q.z; d[3] = q.w;
        }
    }
    __syncthreads();   // publish off tables + staged pose

    // --- Tree walk: symmetric chains packed 2-wide, spine/head scalar ------
    if (inb) {
        float* mp = &s[tid * ROW];
        const ull neg1 = pk2(-1.0f, -1.0f);
        float G[9], t[3];
        ull  PG[9], PT[3];

        // Root (scalar)
        rodr3(mp[0], mp[1], mp[2], G);
        {
            const float4 o0 = off4[0];
            t[0] = o0.x + tr0; t[1] = o0.y + tr1; t[2] = o0.z + tr2;
            mp[0] = t[0]; mp[1] = t[1]; mp[2] = t[2];
        }

        // Broadcast root into packed legs; spine continues scalar in G.
#pragma unroll
        for (int i = 0; i < 9; i++) PG[i] = pk2(G[i], G[i]);
        PT[0] = pk2(t[0], t[0]); PT[1] = pk2(t[1], t[1]); PT[2] = pk2(t[2], t[2]);

        // Interleaved: packed legs (1|2)->(4|5)->(7|8)->(10|11) + scalar spine 3->6->9
        stepPair<1, 0>(PG, PT, mp, offp, neg1);
        stepNL<3>(G, t, mp, off4);
        stepPair<4, 1>(PG, PT, mp, offp, neg1);
        stepNL<6>(G, t, mp, off4);
        stepPair<7, 2>(PG, PT, mp, offp, neg1);
        stepNL<9>(G, t, mp, off4);
        leafPair<10, 3>(PG, PT, mp, offp);

        // Broadcast joint 9 into packed arms; head continues scalar in G.
#pragma unroll
        for (int i = 0; i < 9; i++) PG[i] = pk2(G[i], G[i]);
        PT[0] = pk2(t[0], t[0]); PT[1] = pk2(t[1], t[1]); PT[2] = pk2(t[2], t[2]);

        // Interleaved: packed arms (13|14)->(16|17)->(18|19)->(20|21)->(22|23)
        // + scalar head 12 -> 15(leaf)
        stepPair<13, 4>(PG, PT, mp, offp, neg1);
        stepNL<12>(G, t, mp, off4);
        stepPair<16, 5>(PG, PT, mp, offp, neg1);
        stepLeaf<15>(G, t, mp, off4);
        stepPair<18, 6>(PG, PT, mp, offp, neg1);
        stepPair<20, 7>(PG, PT, mp, offp, neg1);
        leafPair<22, 8>(PG, PT, mp, offp);
    }
    __syncwarp();   // drain reads only this warp's rows

    // --- Drain: smem rows (J_posed) -> coalesced float4 stores (R1 form) ---
    float4* go = reinterpret_cast<float4*>(out) + (long long)wb0 * 18;
#pragma unroll
    for (int k = 0; k < 18; k++) {
        const int v = lane + k * 32;
        const int b = v / 18, c = v % 18;
        if (wb0 + b < B) {
            const float* sp = &sw[b * ROW + c * 4];
            go[v] = make_float4(sp[0], sp[1], sp[2], sp[3]);
        }
    }
}

extern "C" void kernel_launch(void* const* d_in, const int* in_sizes, int n_in,
                              void* d_out, int out_size) {
    // Identify inputs by element count (expected order: pose, trans, J, parents)
    int ip = 0;
    long long mx = -1;
    for (int i = 0; i < n_in; i++)
        if ((long long)in_sizes[i] > mx) { mx = in_sizes[i]; ip = i; }
    const int B = in_sizes[ip] / 72;            // pose: [B,24,3]

    int it = -1, ij = -1;
    for (int i = 0; i < n_in; i++) {
        if (i == ip) continue;
        if (in_sizes[i] == B * 3) it = i;        // trans: [B,3]
        else if (in_sizes[i] == 24 * 16) ij = i; // J: [24,4,4]
    }
    if (it < 0) it = 1;
    if (ij < 0) ij = 2;

    cudaFuncSetAttribute(skel_kernel,
                         cudaFuncAttributePreferredSharedMemoryCarveout, 100);

    const int grid = (B + BLK - 1) / BLK;
    skel_kernel<<<grid, BLK>>>((const float*)d_in[ip],
                               (const float*)d_in[it],
                               (const float*)d_in[ij],
                               (float*)d_out, B);
}

// round 7
// speedup vs baseline: 1.0135x; 1.0118x over previous
#include <cuda_runtime.h>

#define BLK 128
#define ROW 73   // padded smem row stride; tid*73 mod 32 ≡ tid*9, gcd(9,32)=1 -> conflict-free

typedef unsigned long long ull;

// ---- packed fp32x2 primitives (sm_103a) -----------------------------------
__device__ __forceinline__ ull pk2(float lo, float hi) {
    ull r; asm("mov.b64 %0, {%1,%2};" : "=l"(r) : "f"(lo), "f"(hi)); return r;
}
__device__ __forceinline__ void upk2(ull v, float& lo, float& hi) {
    asm("mov.b64 {%0,%1}, %2;" : "=f"(lo), "=f"(hi) : "l"(v));
}
__device__ __forceinline__ ull f2fma(ull a, ull b, ull c) {
    ull d; asm("fma.rn.f32x2 %0, %1, %2, %3;" : "=l"(d) : "l"(a), "l"(b), "l"(c)); return d;
}
__device__ __forceinline__ ull f2mul(ull a, ull b) {
    ull d; asm("mul.rn.f32x2 %0, %1, %2;" : "=l"(d) : "l"(a), "l"(b)); return d;
}
__device__ __forceinline__ ull f2add(ull a, ull b) {
    ull d; asm("add.rn.f32x2 %0, %1, %2;" : "=l"(d) : "l"(a), "l"(b)); return d;
}

// ---- scalar Taylor polys (immediate constants -> no constant registers) ---
__device__ __forceinline__ float polyA(float u) {
    float A = fmaf(u,  2.75573192e-6f, -1.98412698e-4f);
    A = fmaf(A, u,  8.33333333e-3f);
    A = fmaf(A, u, -1.66666667e-1f);
    return fmaf(A, u, 1.0f);
}
__device__ __forceinline__ float polyB(float u) {
    float Bv = fmaf(u,  2.75573192e-7f, -2.48015873e-5f);
    Bv = fmaf(Bv, u,  1.38888889e-3f);
    Bv = fmaf(Bv, u, -4.16666667e-2f);
    return fmaf(Bv, u, 0.5f);
}

// ---- scalar Rodrigues ------------------------------------------------------
__device__ __forceinline__ void rodr3(float x, float y, float z, float R[9]) {
    const float u = fmaf(x, x, fmaf(y, y, z * z));
    const float A = polyA(u), Bv = polyB(u);
    const float c = fmaf(-Bv, u, 1.0f);
    const float Bx = Bv * x, By = Bv * y, Bz = Bv * z;
    const float Ax = A * x,  Ay = A * y,  Az = A * z;
    const float Bxy = Bx * y, Bxz = Bx * z, Byz = By * z;
    R[0] = fmaf(Bx, x, c);  R[4] = fmaf(By, y, c);  R[8] = fmaf(Bz, z, c);
    R[1] = Bxy - Az;  R[3] = Bxy + Az;
    R[2] = Bxz + Ay;  R[6] = Bxz - Ay;
    R[5] = Byz - Ax;  R[7] = Byz + Ax;
}

// ---- packed Rodrigues: polys scalar per half, matrix build packed ----------
__device__ __forceinline__ void rodr2(ull x, ull y, ull z, ull R[9], ull neg1) {
    const ull u = f2fma(x, x, f2fma(y, y, f2mul(z, z)));
    float ul, uh; upk2(u, ul, uh);
    const float Al = polyA(ul), Ah = polyA(uh);
    const float Bl = polyB(ul), Bh = polyB(uh);
    const ull A  = pk2(Al, Ah);
    const ull Bv = pk2(Bl, Bh);
    const ull c  = pk2(fmaf(-Bl, ul, 1.0f), fmaf(-Bh, uh, 1.0f));

    const ull Bx = f2mul(Bv, x), By = f2mul(Bv, y), Bz = f2mul(Bv, z);
    const ull Ax = f2mul(A, x),  Ay = f2mul(A, y),  Az = f2mul(A, z);
    const ull Bxy = f2mul(Bx, y), Bxz = f2mul(Bx, z), Byz = f2mul(By, z);

    R[0] = f2fma(Bx, x, c);  R[4] = f2fma(By, y, c);  R[8] = f2fma(Bz, z, c);
    R[1] = f2fma(Az, neg1, Bxy);  R[3] = f2add(Bxy, Az);
    R[2] = f2add(Bxz, Ay);        R[6] = f2fma(Ay, neg1, Bxz);
    R[5] = f2fma(Ax, neg1, Byz);  R[7] = f2add(Byz, Ax);
}

// ---- scalar non-leaf / leaf steps; offsets via uniform __ldg of Jm ---------
template <int J>
__device__ __forceinline__ void stepNL(float G[9], float t[3],
                                       float* __restrict__ mp,
                                       const float* __restrict__ Jm) {
    const float ox = __ldg(&Jm[J*16+3]), oy = __ldg(&Jm[J*16+7]), oz = __ldg(&Jm[J*16+11]);
    const float n0 = fmaf(G[0], ox, fmaf(G[1], oy, fmaf(G[2], oz, t[0])));
    const float n1 = fmaf(G[3], ox, fmaf(G[4], oy, fmaf(G[5], oz, t[1])));
    const float n2 = fmaf(G[6], ox, fmaf(G[7], oy, fmaf(G[8], oz, t[2])));
    float R[9];
    rodr3(mp[J*3+0], mp[J*3+1], mp[J*3+2], R);
#pragma unroll
    for (int r = 0; r < 3; r++) {
        const float g0 = G[r*3+0], g1 = G[r*3+1], g2 = G[r*3+2];
        G[r*3+0] = fmaf(g0, R[0], fmaf(g1, R[3], g2 * R[6]));
        G[r*3+1] = fmaf(g0, R[1], fmaf(g1, R[4], g2 * R[7]));
        G[r*3+2] = fmaf(g0, R[2], fmaf(g1, R[5], g2 * R[8]));
    }
    t[0] = n0; t[1] = n1; t[2] = n2;
    mp[J*3+0] = n0; mp[J*3+1] = n1; mp[J*3+2] = n2;
}
template <int J>
__device__ __forceinline__ void stepLeaf(const float G[9], const float t[3],
                                         float* __restrict__ mp,
                                         const float* __restrict__ Jm) {
    const float ox = __ldg(&Jm[J*16+3]), oy = __ldg(&Jm[J*16+7]), oz = __ldg(&Jm[J*16+11]);
    mp[J*3+0] = fmaf(G[0], ox, fmaf(G[1], oy, fmaf(G[2], oz, t[0])));
    mp[J*3+1] = fmaf(G[3], ox, fmaf(G[4], oy, fmaf(G[5], oz, t[1])));
    mp[J*3+2] = fmaf(G[6], ox, fmaf(G[7], oy, fmaf(G[8], oz, t[2])));
}

// ---- packed pair steps for symmetric joints (J, J+1) -----------------------
template <int J>
__device__ __forceinline__ void stepPair(ull G[9], ull t[3],
                                         float* __restrict__ mp,
                                         const float* __restrict__ Jm,
                                         ull neg1) {
    const ull ox = pk2(__ldg(&Jm[J*16+3]),  __ldg(&Jm[(J+1)*16+3]));
    const ull oy = pk2(__ldg(&Jm[J*16+7]),  __ldg(&Jm[(J+1)*16+7]));
    const ull oz = pk2(__ldg(&Jm[J*16+11]), __ldg(&Jm[(J+1)*16+11]));
    const ull n0 = f2fma(G[0], ox, f2fma(G[1], oy, f2fma(G[2], oz, t[0])));
    const ull n1 = f2fma(G[3], ox, f2fma(G[4], oy, f2fma(G[5], oz, t[1])));
    const ull n2 = f2fma(G[6], ox, f2fma(G[7], oy, f2fma(G[8], oz, t[2])));

    const ull px = pk2(mp[3*J+0], mp[3*J+3]);   // lo = joint J, hi = joint J+1
    const ull py = pk2(mp[3*J+1], mp[3*J+4]);
    const ull pz = pk2(mp[3*J+2], mp[3*J+5]);
    ull R[9];
    rodr2(px, py, pz, R, neg1);

#pragma unroll
    for (int r = 0; r < 3; r++) {
        const ull g0 = G[r*3+0], g1 = G[r*3+1], g2 = G[r*3+2];
        G[r*3+0] = f2fma(g0, R[0], f2fma(g1, R[3], f2mul(g2, R[6])));
        G[r*3+1] = f2fma(g0, R[1], f2fma(g1, R[4], f2mul(g2, R[7])));
        G[r*3+2] = f2fma(g0, R[2], f2fma(g1, R[5], f2mul(g2, R[8])));
    }
    t[0] = n0; t[1] = n1; t[2] = n2;
    float a, b;
    upk2(n0, a, b); mp[3*J+0] = a; mp[3*J+3] = b;
    upk2(n1, a, b); mp[3*J+1] = a; mp[3*J+4] = b;
    upk2(n2, a, b); mp[3*J+2] = a; mp[3*J+5] = b;
}
template <int J>
__device__ __forceinline__ void leafPair(const ull G[9], const ull t[3],
                                         float* __restrict__ mp,
                                         const float* __restrict__ Jm) {
    const ull ox = pk2(__ldg(&Jm[J*16+3]),  __ldg(&Jm[(J+1)*16+3]));
    const ull oy = pk2(__ldg(&Jm[J*16+7]),  __ldg(&Jm[(J+1)*16+7]));
    const ull oz = pk2(__ldg(&Jm[J*16+11]), __ldg(&Jm[(J+1)*16+11]));
    const ull n0 = f2fma(G[0], ox, f2fma(G[1], oy, f2fma(G[2], oz, t[0])));
    const ull n1 = f2fma(G[3], ox, f2fma(G[4], oy, f2fma(G[5], oz, t[1])));
    const ull n2 = f2fma(G[6], ox, f2fma(G[7], oy, f2fma(G[8], oz, t[2])));
    float a, b;
    upk2(n0, a, b); mp[3*J+0] = a; mp[3*J+3] = b;
    upk2(n1, a, b); mp[3*J+1] = a; mp[3*J+4] = b;
    upk2(n2, a, b); mp[3*J+2] = a; mp[3*J+5] = b;
}

__global__ void __launch_bounds__(BLK, 4)
skel_kernel(const float* __restrict__ pose,
            const float* __restrict__ trans,
            const float* __restrict__ Jm,
            float* __restrict__ out, int B) {
    __shared__ float s[BLK * ROW];

    const int tid  = threadIdx.x;
    const int lane = tid & 31;
    const int wrp  = tid >> 5;
    const int b0   = blockIdx.x * BLK;
    const int wb0  = b0 + wrp * 32;
    const int myb  = b0 + tid;
    const bool inb = (myb < B);

    // Hoisted trans loads (DRAM, consumed much later).
    float tr0 = 0.f, tr1 = 0.f, tr2 = 0.f;
    if (inb) { tr0 = trans[myb*3+0]; tr1 = trans[myb*3+1]; tr2 = trans[myb*3+2]; }

    // --- Stage pose (warp-autonomous): coalesced float4 -> padded smem rows.
    // NO block barrier anywhere: warps slip freely, so while one warp computes
    // the others' DRAM loads are in flight (continuous DRAM demand instead of
    // synchronized burst-then-idle).
    const float4* gp = reinterpret_cast<const float4*>(pose) + (long long)wb0 * 18;
    float* sw = &s[wrp * 32 * ROW];
#pragma unroll
    for (int k = 0; k < 18; k++) {
        const int v = lane + k * 32;
        const int b = v / 18, c = v % 18;
        if (wb0 + b < B) {
            const float4 q = gp[v];
            float* d = &sw[b * ROW + c * 4];
            d[0] = q.x; d[1] = q.y; d[2] = q.z; d[3] = q.w;
        }
    }
    __syncwarp();   // this warp's rows are staged

    // --- Tree walk: symmetric chains packed 2-wide (f32x2), spine/head scalar
    if (inb) {
        float* mp = &s[tid * ROW];
        const ull neg1 = pk2(-1.0f, -1.0f);
        float G[9], t[3];
        ull  PG[9], PT[3];

        // Root (scalar); trans folds into the root translation.
        rodr3(mp[0], mp[1], mp[2], G);
        {
            const float ox = __ldg(&Jm[3]), oy = __ldg(&Jm[7]), oz = __ldg(&Jm[11]);
            t[0] = ox + tr0; t[1] = oy + tr1; t[2] = oz + tr2;
            mp[0] = t[0]; mp[1] = t[1]; mp[2] = t[2];
        }

        // Broadcast root into packed legs; spine continues scalar in G.
#pragma unroll
        for (int i = 0; i < 9; i++) PG[i] = pk2(G[i], G[i]);
        PT[0] = pk2(t[0], t[0]); PT[1] = pk2(t[1], t[1]); PT[2] = pk2(t[2], t[2]);

        // Interleaved: packed legs (1|2)->(4|5)->(7|8)->(10|11) + scalar spine 3->6->9
        stepPair<1>(PG, PT, mp, Jm, neg1);
        stepNL<3>(G, t, mp, Jm);
        stepPair<4>(PG, PT, mp, Jm, neg1);
        stepNL<6>(G, t, mp, Jm);
        stepPair<7>(PG, PT, mp, Jm, neg1);
        stepNL<9>(G, t, mp, Jm);
        leafPair<10>(PG, PT, mp, Jm);

        // Broadcast joint 9 into packed arms; head continues scalar in G.
#pragma unroll
        for (int i = 0; i < 9; i++) PG[i] = pk2(G[i], G[i]);
        PT[0] = pk2(t[0], t[0]); PT[1] = pk2(t[1], t[1]); PT[2] = pk2(t[2], t[2]);

        // Interleaved: packed arms (13|14)->(16|17)->(18|19)->(20|21)->(22|23)
        // + scalar head 12 -> 15(leaf)
        stepPair<13>(PG, PT, mp, Jm, neg1);
        stepNL<12>(G, t, mp, Jm);
        stepPair<16>(PG, PT, mp, Jm, neg1);
        stepLeaf<15>(G, t, mp, Jm);
        stepPair<18>(PG, PT, mp, Jm, neg1);
        stepPair<20>(PG, PT, mp, Jm, neg1);
        leafPair<22>(PG, PT, mp, Jm);
    }
    __syncwarp();   // drain reads only this warp's rows

    // --- Drain (warp-autonomous): smem rows -> coalesced float4 stores -----
    float4* go = reinterpret_cast<float4*>(out) + (long long)wb0 * 18;
#pragma unroll
    for (int k = 0; k < 18; k++) {
        const int v = lane + k * 32;
        const int b = v / 18, c = v % 18;
        if (wb0 + b < B) {
            const float* sp = &sw[b * ROW + c * 4];
            go[v] = make_float4(sp[0], sp[1], sp[2], sp[3]);
        }
    }
}

extern "C" void kernel_launch(void* const* d_in, const int* in_sizes, int n_in,
                              void* d_out, int out_size) {
    // Identify inputs by element count (expected order: pose, trans, J, parents)
    int ip = 0;
    long long mx = -1;
    for (int i = 0; i < n_in; i++)
        if ((long long)in_sizes[i] > mx) { mx = in_sizes[i]; ip = i; }
    const int B = in_sizes[ip] / 72;            // pose: [B,24,3]

    int it = -1, ij = -1;
    for (int i = 0; i < n_in; i++) {
        if (i == ip) continue;
        if (in_sizes[i] == B * 3) it = i;        // trans: [B,3]
        else if (in_sizes[i] == 24 * 16) ij = i; // J: [24,4,4]
    }
    if (it < 0) it = 1;
    if (ij < 0) ij = 2;

    cudaFuncSetAttribute(skel_kernel,
                         cudaFuncAttributePreferredSharedMemoryCarveout, 100);

    const int grid = (B + BLK - 1) / BLK;
    skel_kernel<<<grid, BLK>>>((const float*)d_in[ip],
                               (const float*)d_in[it],
                               (const float*)d_in[ij],
                               (float*)d_out, B);
}

// round 8
// speedup vs baseline: 1.1366x; 1.1214x over previous
#include <cuda_runtime.h>

#define BLK 128
#define ROW 73   // odd row stride: compute-phase per-thread rows are conflict-free

typedef unsigned long long ull;

__constant__ float JC[24 * 16];   // rest-pose J matrices (offsets at [j*16+{3,7,11}])

// ---- packed fp32x2 primitives (sm_103a) -----------------------------------
__device__ __forceinline__ ull pk2(float lo, float hi) {
    ull r; asm("mov.b64 %0, {%1,%2};" : "=l"(r) : "f"(lo), "f"(hi)); return r;
}
__device__ __forceinline__ void upk2(ull v, float& lo, float& hi) {
    asm("mov.b64 {%0,%1}, %2;" : "=f"(lo), "=f"(hi) : "l"(v));
}
__device__ __forceinline__ ull f2fma(ull a, ull b, ull c) {
    ull d; asm("fma.rn.f32x2 %0, %1, %2, %3;" : "=l"(d) : "l"(a), "l"(b), "l"(c)); return d;
}
__device__ __forceinline__ ull f2mul(ull a, ull b) {
    ull d; asm("mul.rn.f32x2 %0, %1, %2;" : "=l"(d) : "l"(a), "l"(b)); return d;
}
__device__ __forceinline__ ull f2add(ull a, ull b) {
    ull d; asm("add.rn.f32x2 %0, %1, %2;" : "=l"(d) : "l"(a), "l"(b)); return d;
}

// ---- scalar Taylor polys (immediate constants) -----------------------------
__device__ __forceinline__ float polyA(float u) {
    float A = fmaf(u,  2.75573192e-6f, -1.98412698e-4f);
    A = fmaf(A, u,  8.33333333e-3f);
    A = fmaf(A, u, -1.66666667e-1f);
    return fmaf(A, u, 1.0f);
}
__device__ __forceinline__ float polyB(float u) {
    float Bv = fmaf(u,  2.75573192e-7f, -2.48015873e-5f);
    Bv = fmaf(Bv, u,  1.38888889e-3f);
    Bv = fmaf(Bv, u, -4.16666667e-2f);
    return fmaf(Bv, u, 0.5f);
}

// ---- scalar Rodrigues ------------------------------------------------------
__device__ __forceinline__ void rodr3(float x, float y, float z, float R[9]) {
    const float u = fmaf(x, x, fmaf(y, y, z * z));
    const float A = polyA(u), Bv = polyB(u);
    const float c = fmaf(-Bv, u, 1.0f);
    const float Bx = Bv * x, By = Bv * y, Bz = Bv * z;
    const float Ax = A * x,  Ay = A * y,  Az = A * z;
    const float Bxy = Bx * y, Bxz = Bx * z, Byz = By * z;
    R[0] = fmaf(Bx, x, c);  R[4] = fmaf(By, y, c);  R[8] = fmaf(Bz, z, c);
    R[1] = Bxy - Az;  R[3] = Bxy + Az;
    R[2] = Bxz + Ay;  R[6] = Bxz - Ay;
    R[5] = Byz - Ax;  R[7] = Byz + Ax;
}

// ---- packed Rodrigues: polys scalar per half, matrix build packed ----------
__device__ __forceinline__ void rodr2(ull x, ull y, ull z, ull R[9], ull neg1) {
    const ull u = f2fma(x, x, f2fma(y, y, f2mul(z, z)));
    float ul, uh; upk2(u, ul, uh);
    const float Al = polyA(ul), Ah = polyA(uh);
    const float Bl = polyB(ul), Bh = polyB(uh);
    const ull A  = pk2(Al, Ah);
    const ull Bv = pk2(Bl, Bh);
    const ull c  = pk2(fmaf(-Bl, ul, 1.0f), fmaf(-Bh, uh, 1.0f));

    const ull Bx = f2mul(Bv, x), By = f2mul(Bv, y), Bz = f2mul(Bv, z);
    const ull Ax = f2mul(A, x),  Ay = f2mul(A, y),  Az = f2mul(A, z);
    const ull Bxy = f2mul(Bx, y), Bxz = f2mul(Bx, z), Byz = f2mul(By, z);

    R[0] = f2fma(Bx, x, c);  R[4] = f2fma(By, y, c);  R[8] = f2fma(Bz, z, c);
    R[1] = f2fma(Az, neg1, Bxy);  R[3] = f2add(Bxy, Az);
    R[2] = f2add(Bxz, Ay);        R[6] = f2fma(Ay, neg1, Bxz);
    R[5] = f2fma(Ax, neg1, Byz);  R[7] = f2add(Byz, Ax);
}

// ---- scalar non-leaf / leaf steps; offsets from __constant__ ----------------
template <int J>
__device__ __forceinline__ void stepNL(float G[9], float t[3],
                                       float* __restrict__ mp) {
    const float ox = JC[J*16+3], oy = JC[J*16+7], oz = JC[J*16+11];
    const float n0 = fmaf(G[0], ox, fmaf(G[1], oy, fmaf(G[2], oz, t[0])));
    const float n1 = fmaf(G[3], ox, fmaf(G[4], oy, fmaf(G[5], oz, t[1])));
    const float n2 = fmaf(G[6], ox, fmaf(G[7], oy, fmaf(G[8], oz, t[2])));
    float R[9];
    rodr3(mp[J*3+0], mp[J*3+1], mp[J*3+2], R);
#pragma unroll
    for (int r = 0; r < 3; r++) {
        const float g0 = G[r*3+0], g1 = G[r*3+1], g2 = G[r*3+2];
        G[r*3+0] = fmaf(g0, R[0], fmaf(g1, R[3], g2 * R[6]));
        G[r*3+1] = fmaf(g0, R[1], fmaf(g1, R[4], g2 * R[7]));
        G[r*3+2] = fmaf(g0, R[2], fmaf(g1, R[5], g2 * R[8]));
    }
    t[0] = n0; t[1] = n1; t[2] = n2;
    mp[J*3+0] = n0; mp[J*3+1] = n1; mp[J*3+2] = n2;
}
template <int J>
__device__ __forceinline__ void stepLeaf(const float G[9], const float t[3],
                                         float* __restrict__ mp) {
    const float ox = JC[J*16+3], oy = JC[J*16+7], oz = JC[J*16+11];
    mp[J*3+0] = fmaf(G[0], ox, fmaf(G[1], oy, fmaf(G[2], oz, t[0])));
    mp[J*3+1] = fmaf(G[3], ox, fmaf(G[4], oy, fmaf(G[5], oz, t[1])));
    mp[J*3+2] = fmaf(G[6], ox, fmaf(G[7], oy, fmaf(G[8], oz, t[2])));
}

// ---- packed pair steps for symmetric joints (J, J+1) -----------------------
template <int J>
__device__ __forceinline__ void stepPair(ull G[9], ull t[3],
                                         float* __restrict__ mp, ull neg1) {
    const ull ox = pk2(JC[J*16+3],  JC[(J+1)*16+3]);
    const ull oy = pk2(JC[J*16+7],  JC[(J+1)*16+7]);
    const ull oz = pk2(JC[J*16+11], JC[(J+1)*16+11]);
    const ull n0 = f2fma(G[0], ox, f2fma(G[1], oy, f2fma(G[2], oz, t[0])));
    const ull n1 = f2fma(G[3], ox, f2fma(G[4], oy, f2fma(G[5], oz, t[1])));
    const ull n2 = f2fma(G[6], ox, f2fma(G[7], oy, f2fma(G[8], oz, t[2])));

    const ull px = pk2(mp[3*J+0], mp[3*J+3]);   // lo = joint J, hi = joint J+1
    const ull py = pk2(mp[3*J+1], mp[3*J+4]);
    const ull pz = pk2(mp[3*J+2], mp[3*J+5]);
    ull R[9];
    rodr2(px, py, pz, R, neg1);

#pragma unroll
    for (int r = 0; r < 3; r++) {
        const ull g0 = G[r*3+0], g1 = G[r*3+1], g2 = G[r*3+2];
        G[r*3+0] = f2fma(g0, R[0], f2fma(g1, R[3], f2mul(g2, R[6])));
        G[r*3+1] = f2fma(g0, R[1], f2fma(g1, R[4], f2mul(g2, R[7])));
        G[r*3+2] = f2fma(g0, R[2], f2fma(g1, R[5], f2mul(g2, R[8])));
    }
    t[0] = n0; t[1] = n1; t[2] = n2;
    float a, b;
    upk2(n0, a, b); mp[3*J+0] = a; mp[3*J+3] = b;
    upk2(n1, a, b); mp[3*J+1] = a; mp[3*J+4] = b;
    upk2(n2, a, b); mp[3*J+2] = a; mp[3*J+5] = b;
}
template <int J>
__device__ __forceinline__ void leafPair(const ull G[9], const ull t[3],
                                         float* __restrict__ mp) {
    const ull ox = pk2(JC[J*16+3],  JC[(J+1)*16+3]);
    const ull oy = pk2(JC[J*16+7],  JC[(J+1)*16+7]);
    const ull oz = pk2(JC[J*16+11], JC[(J+1)*16+11]);
    const ull n0 = f2fma(G[0], ox, f2fma(G[1], oy, f2fma(G[2], oz, t[0])));
    const ull n1 = f2fma(G[3], ox, f2fma(G[4], oy, f2fma(G[5], oz, t[1])));
    const ull n2 = f2fma(G[6], ox, f2fma(G[7], oy, f2fma(G[8], oz, t[2])));
    float a, b;
    upk2(n0, a, b); mp[3*J+0] = a; mp[3*J+3] = b;
    upk2(n1, a, b); mp[3*J+1] = a; mp[3*J+4] = b;
    upk2(n2, a, b); mp[3*J+2] = a; mp[3*J+5] = b;
}

__global__ void __launch_bounds__(BLK, 4)
skel_kernel(const float* __restrict__ pose,
            const float* __restrict__ trans,
            float* __restrict__ out, int B) {
    __shared__ float s[BLK * ROW];

    const int tid  = threadIdx.x;
    const int lane = tid & 31;
    const int wrp  = tid >> 5;
    const int b0   = blockIdx.x * BLK;
    const int wb0  = b0 + wrp * 32;
    const int myb  = b0 + tid;
    const bool inb = (myb < B);

    // Hoisted trans loads (DRAM, consumed much later).
    float tr0 = 0.f, tr1 = 0.f, tr2 = 0.f;
    if (inb) { tr0 = trans[myb*3+0]; tr1 = trans[myb*3+1]; tr2 = trans[myb*3+2]; }

    // --- Word-granular conflict-free transpose bases -----------------------
    // Global word v = lane + 32k maps to smem word 73*(v/72) + v%72 = v + b.
    // Period: 32*9 = 288 = 4*72, so 9 base offsets cover all 72 k's with
    // compile-time increments (+292 smem words / +288 global words per j).
    int base[9];
    {
        int bb = 0, cc = lane;
#pragma unroll
        for (int p = 0; p < 9; p++) {
            base[p] = 73 * bb + cc;
            cc += 32;
            if (cc >= 72) { cc -= 72; bb++; }
        }
    }

    // --- Stage: coalesced scalar LDG -> conflict-free scalar STS -----------
    // Warp-autonomous (no block barrier anywhere): warps slip freely.
    const float* gw = pose + (long long)wb0 * 72;
    float* sw = s + wrp * 32 * ROW;
    if (wb0 + 32 <= B) {
#pragma unroll
        for (int j = 0; j < 8; j++)
#pragma unroll
            for (int p = 0; p < 9; p++)
                sw[base[p] + 292 * j] = gw[lane + 32 * p + 288 * j];
    } else {
#pragma unroll
        for (int j = 0; j < 8; j++)
#pragma unroll
            for (int p = 0; p < 9; p++) {
                const int v = lane + 32 * p + 288 * j;
                if (wb0 + v / 72 < B)
                    sw[base[p] + 292 * j] = gw[v];
            }
    }
    __syncwarp();   // this warp's rows are staged

    // --- Tree walk: symmetric chains packed 2-wide (f32x2), spine/head scalar
    if (inb) {
        float* mp = &s[tid * ROW];
        const ull neg1 = pk2(-1.0f, -1.0f);
        float G[9], t[3];
        ull  PG[9], PT[3];

        // Root (scalar); trans folds into the root translation.
        rodr3(mp[0], mp[1], mp[2], G);
        t[0] = JC[3]  + tr0;
        t[1] = JC[7]  + tr1;
        t[2] = JC[11] + tr2;
        mp[0] = t[0]; mp[1] = t[1]; mp[2] = t[2];

        // Broadcast root into packed legs; spine continues scalar in G.
#pragma unroll
        for (int i = 0; i < 9; i++) PG[i] = pk2(G[i], G[i]);
        PT[0] = pk2(t[0], t[0]); PT[1] = pk2(t[1], t[1]); PT[2] = pk2(t[2], t[2]);

        // Interleaved: packed legs (1|2)->(4|5)->(7|8)->(10|11) + scalar spine 3->6->9
        stepPair<1>(PG, PT, mp, neg1);
        stepNL<3>(G, t, mp);
        stepPair<4>(PG, PT, mp, neg1);
        stepNL<6>(G, t, mp);
        stepPair<7>(PG, PT, mp, neg1);
        stepNL<9>(G, t, mp);
        leafPair<10>(PG, PT, mp);

        // Broadcast joint 9 into packed arms; head continues scalar in G.
#pragma unroll
        for (int i = 0; i < 9; i++) PG[i] = pk2(G[i], G[i]);
        PT[0] = pk2(t[0], t[0]); PT[1] = pk2(t[1], t[1]); PT[2] = pk2(t[2], t[2]);

        // Interleaved: packed arms (13|14)->(16|17)->(18|19)->(20|21)->(22|23)
        // + scalar head 12 -> 15(leaf)
        stepPair<13>(PG, PT, mp, neg1);
        stepNL<12>(G, t, mp);
        stepPair<16>(PG, PT, mp, neg1);
        stepLeaf<15>(G, t, mp);
        stepPair<18>(PG, PT, mp, neg1);
        stepPair<20>(PG, PT, mp, neg1);
        leafPair<22>(PG, PT, mp);
    }
    __syncwarp();   // drain reads only this warp's rows

    // --- Drain: conflict-free scalar LDS -> coalesced scalar STG -----------
    float* go = out + (long long)wb0 * 72;
    if (wb0 + 32 <= B) {
#pragma unroll
        for (int j = 0; j < 8; j++)
#pragma unroll
            for (int p = 0; p < 9; p++)
                go[lane + 32 * p + 288 * j] = sw[base[p] + 292 * j];
    } else {
#pragma unroll
        for (int j = 0; j < 8; j++)
#pragma unroll
            for (int p = 0; p < 9; p++) {
                const int v = lane + 32 * p + 288 * j;
                if (wb0 + v / 72 < B)
                    go[v] = sw[base[p] + 292 * j];
            }
    }
}

extern "C" void kernel_launch(void* const* d_in, const int* in_sizes, int n_in,
                              void* d_out, int out_size) {
    // Identify inputs by element count (expected order: pose, trans, J, parents)
    int ip = 0;
    long long mx = -1;
    for (int i = 0; i < n_in; i++)
        if ((long long)in_sizes[i] > mx) { mx = in_sizes[i]; ip = i; }
    const int B = in_sizes[ip] / 72;            // pose: [B,24,3]

    int it = -1, ij = -1;
    for (int i = 0; i < n_in; i++) {
        if (i == ip) continue;
        if (in_sizes[i] == B * 3) it = i;        // trans: [B,3]
        else if (in_sizes[i] == 24 * 16) ij = i; // J: [24,4,4]
    }
    if (it < 0) it = 1;
    if (ij < 0) ij = 2;

    // J -> constant memory (device-to-device async copy; graph-capturable).
    cudaMemcpyToSymbolAsync(JC, d_in[ij], 24 * 16 * sizeof(float), 0,
                            cudaMemcpyDeviceToDevice, 0);

    cudaFuncSetAttribute(skel_kernel,
                         cudaFuncAttributePreferredSharedMemoryCarveout, 100);

    const int grid = (B + BLK - 1) / BLK;
    skel_kernel<<<grid, BLK>>>((const float*)d_in[ip],
                               (const float*)d_in[it],
                               (float*)d_out, B);
}